// round 1
// baseline (speedup 1.0000x reference)
#include <cuda_runtime.h>
#include <math.h>

#define T_SEQ   2048
#define HID     2048
#define NQH     16
#define NKVH    4
#define HD      128
#define QGN     4096   // wq output width (q+gate)
#define KVN     512    // wk/wv output width

// ---------------- static scratch (no allocs allowed) ----------------
__device__ float g_xqg[T_SEQ * QGN];          // 32 MB  x@wq
__device__ float g_xk [T_SEQ * KVN];          //  4 MB  x@wk
__device__ float g_xv [T_SEQ * KVN];          //  4 MB  x@wv
__device__ float g_qn [NQH  * T_SEQ * HD];    // 16 MB  normed+roped q, head-major
__device__ float g_kn [NKVH * T_SEQ * HD];    //  4 MB
__device__ float g_vt [NKVH * T_SEQ * HD];    //  4 MB  v transposed head-major
__device__ float g_y  [T_SEQ * HID];          // 16 MB  gated attention out

// ---------------- SGEMM: C[M,N] = A[M,K] @ B[K,N], all row-major ----------------
// 128x128 tile, BK=16, 256 threads, 8x8 microtile. M,N,K multiples of 128/16.
__global__ __launch_bounds__(256) void sgemm128(
    const float* __restrict__ A, const float* __restrict__ B,
    float* __restrict__ C, int M, int N, int K)
{
    __shared__ __align__(16) float As[16][128];   // transposed A tile
    __shared__ __align__(16) float Bs[16][128];

    const int tid = threadIdx.x;
    const int ty = tid >> 4, tx = tid & 15;
    const int bm = blockIdx.y * 128, bn = blockIdx.x * 128;

    // A loader: thread covers row tid/2, cols (tid%2)*8 .. +7
    const int arow = tid >> 1;
    const int acol = (tid & 1) * 8;
    // B loader: row tid/16, cols (tid%16)*8
    const int brow = tid >> 4;
    const int bcol = (tid & 15) * 8;

    const float* Ap = A + (size_t)(bm + arow) * K + acol;
    const float* Bp = B + (size_t)brow * N + bn + bcol;

    float acc[8][8];
    #pragma unroll
    for (int i = 0; i < 8; i++)
        #pragma unroll
        for (int j = 0; j < 8; j++) acc[i][j] = 0.f;

    for (int k0 = 0; k0 < K; k0 += 16) {
        float4 a0 = *(const float4*)(Ap);
        float4 a1 = *(const float4*)(Ap + 4);
        float4 b0 = *(const float4*)(Bp);
        float4 b1 = *(const float4*)(Bp + 4);
        As[acol + 0][arow] = a0.x; As[acol + 1][arow] = a0.y;
        As[acol + 2][arow] = a0.z; As[acol + 3][arow] = a0.w;
        As[acol + 4][arow] = a1.x; As[acol + 5][arow] = a1.y;
        As[acol + 6][arow] = a1.z; As[acol + 7][arow] = a1.w;
        *(float4*)&Bs[brow][bcol]     = b0;
        *(float4*)&Bs[brow][bcol + 4] = b1;
        __syncthreads();

        #pragma unroll
        for (int kk = 0; kk < 16; kk++) {
            float4 ra0 = *(const float4*)&As[kk][ty * 8];
            float4 ra1 = *(const float4*)&As[kk][ty * 8 + 4];
            float4 rb0 = *(const float4*)&Bs[kk][tx * 8];
            float4 rb1 = *(const float4*)&Bs[kk][tx * 8 + 4];
            float ra[8] = {ra0.x, ra0.y, ra0.z, ra0.w, ra1.x, ra1.y, ra1.z, ra1.w};
            float rb[8] = {rb0.x, rb0.y, rb0.z, rb0.w, rb1.x, rb1.y, rb1.z, rb1.w};
            #pragma unroll
            for (int i = 0; i < 8; i++)
                #pragma unroll
                for (int j = 0; j < 8; j++)
                    acc[i][j] += ra[i] * rb[j];
        }
        __syncthreads();
        Ap += 16;
        Bp += (size_t)16 * N;
    }

    #pragma unroll
    for (int i = 0; i < 8; i++) {
        float* Cp = C + (size_t)(bm + ty * 8 + i) * N + bn + tx * 8;
        float4 c0 = {acc[i][0], acc[i][1], acc[i][2], acc[i][3]};
        float4 c1 = {acc[i][4], acc[i][5], acc[i][6], acc[i][7]};
        *(float4*)(Cp)     = c0;
        *(float4*)(Cp + 4) = c1;
    }
}

// ---------------- RMSNorm + RoPE + transpose-to-head-major ----------------
// grid: (T_SEQ, 24). jobs 0-15: q heads, 16-19: k heads, 20-23: v copy.
__global__ __launch_bounds__(128) void normrope(
    const float* __restrict__ xqg, const float* __restrict__ xk,
    const float* __restrict__ xv,  const int* __restrict__ input_pos,
    const float* __restrict__ qw,  const float* __restrict__ kw,
    float* __restrict__ qn, float* __restrict__ kn, float* __restrict__ vt)
{
    const int t = blockIdx.x;
    const int job = blockIdx.y;
    const int d = threadIdx.x;

    if (job >= 20) {  // v: plain transpose
        int h = job - 20;
        vt[((size_t)h * T_SEQ + t) * HD + d] = xv[(size_t)t * KVN + h * HD + d];
        return;
    }

    const float* src;
    const float* w;
    float* dst;
    if (job < 16) {
        src = xqg + (size_t)t * QGN + job * 256;      // q part of q|gate
        w = qw;
        dst = qn + ((size_t)job * T_SEQ + t) * HD;
    } else {
        int h = job - 16;
        src = xk + (size_t)t * KVN + h * HD;
        w = kw;
        dst = kn + ((size_t)h * T_SEQ + t) * HD;
    }

    float v = src[d];
    float ss = v * v;
    #pragma unroll
    for (int o = 16; o; o >>= 1) ss += __shfl_xor_sync(0xffffffffu, ss, o);

    __shared__ float warpss[4];
    __shared__ float sh[HD];
    if ((d & 31) == 0) warpss[d >> 5] = ss;
    __syncthreads();
    float tot = warpss[0] + warpss[1] + warpss[2] + warpss[3];
    float nv = v * rsqrtf(tot * (1.f / HD) + 1e-6f) * (1.f + w[d]);
    sh[d] = nv;
    __syncthreads();

    float out;
    if (d < 64) {
        int i = d & 31;                       // rotary pair index
        // inv_freq = 10000^{-i/32}
        float inv = __expf(-(float)i * (9.210340371976184f / 32.f));
        float ang = (float)input_pos[t] * inv;
        float c = cosf(ang), s = sinf(ang);
        if (d < 32) out = sh[d] * c - sh[d + 32] * s;
        else        out = sh[d] * c + sh[d - 32] * s;
    } else {
        out = nv;
    }
    dst[d] = out;
}

// ---------------- flash attention (causal, GQA) + sigmoid gate ----------------
// grid: (T_SEQ/32, NQH). 256 threads. Bq=32, Bk=32.
__global__ __launch_bounds__(256) void attn(
    const float* __restrict__ qn, const float* __restrict__ kn,
    const float* __restrict__ vt, const float* __restrict__ xqg,
    float* __restrict__ y)
{
    const int h = blockIdx.y;
    const int kvh = h >> 2;
    const int q0 = blockIdx.x * 32;

    __shared__ __align__(16) float Qs[32][132];
    __shared__ __align__(16) float KV[32][132];
    __shared__ float Ps[32][32];

    const int t = threadIdx.x;

    // load Q tile: 1024 float4s over 256 threads
    #pragma unroll
    for (int i = 0; i < 4; i++) {
        int fi = t + i * 256;
        int r = fi >> 5, c4 = fi & 31;
        *(float4*)&Qs[r][c4 * 4] =
            *(const float4*)(qn + ((size_t)h * T_SEQ + q0 + r) * HD + c4 * 4);
    }

    const int qr = t >> 3;          // query row 0..31 (8 threads per row)
    const int c0 = (t & 7) * 4;     // score cols
    const int d0 = (t & 7) * 16;    // output dims

    float m = -1e30f, l = 0.f;
    float acc[16];
    #pragma unroll
    for (int i = 0; i < 16; i++) acc[i] = 0.f;

    const int ntiles = (q0 >> 5) + 1;
    const float scale = 0.08838834764831845f;  // 1/sqrt(128)

    for (int kt = 0; kt < ntiles; kt++) {
        const int k0 = kt * 32;
        __syncthreads();   // protect KV from previous PV readers
        #pragma unroll
        for (int i = 0; i < 4; i++) {
            int fi = t + i * 256;
            int r = fi >> 5, c4 = fi & 31;
            *(float4*)&KV[r][c4 * 4] =
                *(const float4*)(kn + ((size_t)kvh * T_SEQ + k0 + r) * HD + c4 * 4);
        }
        __syncthreads();

        float s[4] = {0.f, 0.f, 0.f, 0.f};
        #pragma unroll 8
        for (int kk = 0; kk < 32; kk++) {
            float4 q4 = *(const float4*)&Qs[qr][kk * 4];
            #pragma unroll
            for (int j = 0; j < 4; j++) {
                float4 k4 = *(const float4*)&KV[c0 + j][kk * 4];
                s[j] += q4.x * k4.x + q4.y * k4.y + q4.z * k4.z + q4.w * k4.w;
            }
        }
        #pragma unroll
        for (int j = 0; j < 4; j++) {
            int kcol = k0 + c0 + j;
            float sv = s[j] * scale;
            s[j] = (kcol > q0 + qr) ? -1e30f : sv;
        }
        float rowmax = fmaxf(fmaxf(s[0], s[1]), fmaxf(s[2], s[3]));
        #pragma unroll
        for (int o = 1; o < 8; o <<= 1)
            rowmax = fmaxf(rowmax, __shfl_xor_sync(0xffffffffu, rowmax, o));

        float mn = fmaxf(m, rowmax);
        float corr = __expf(m - mn);
        float p[4], ps = 0.f;
        #pragma unroll
        for (int j = 0; j < 4; j++) { p[j] = __expf(s[j] - mn); ps += p[j]; }
        #pragma unroll
        for (int o = 1; o < 8; o <<= 1) ps += __shfl_xor_sync(0xffffffffu, ps, o);
        l = l * corr + ps;
        m = mn;
        #pragma unroll
        for (int i = 0; i < 16; i++) acc[i] *= corr;
        #pragma unroll
        for (int j = 0; j < 4; j++) Ps[qr][c0 + j] = p[j];
        __syncthreads();

        // load V tile into same buffer
        #pragma unroll
        for (int i = 0; i < 4; i++) {
            int fi = t + i * 256;
            int r = fi >> 5, c4 = fi & 31;
            *(float4*)&KV[r][c4 * 4] =
                *(const float4*)(vt + ((size_t)kvh * T_SEQ + k0 + r) * HD + c4 * 4);
        }
        __syncthreads();

        #pragma unroll 8
        for (int c = 0; c < 32; c++) {
            float pv = Ps[qr][c];
            float4 v0 = *(const float4*)&KV[c][d0];
            float4 v1 = *(const float4*)&KV[c][d0 + 4];
            float4 v2 = *(const float4*)&KV[c][d0 + 8];
            float4 v3 = *(const float4*)&KV[c][d0 + 12];
            acc[0]  += pv * v0.x; acc[1]  += pv * v0.y; acc[2]  += pv * v0.z; acc[3]  += pv * v0.w;
            acc[4]  += pv * v1.x; acc[5]  += pv * v1.y; acc[6]  += pv * v1.z; acc[7]  += pv * v1.w;
            acc[8]  += pv * v2.x; acc[9]  += pv * v2.y; acc[10] += pv * v2.z; acc[11] += pv * v2.w;
            acc[12] += pv * v3.x; acc[13] += pv * v3.y; acc[14] += pv * v3.z; acc[15] += pv * v3.w;
        }
    }

    const float invl = 1.f / l;
    const int tok = q0 + qr;
    const float* gp = xqg + (size_t)tok * QGN + h * 256 + 128 + d0;
    float* yp = y + (size_t)tok * HID + h * HD + d0;
    #pragma unroll
    for (int i = 0; i < 16; i++) {
        float g = gp[i];
        float sg = 1.f / (1.f + __expf(-g));
        yp[i] = acc[i] * invl * sg;
    }
}

// ---------------- launch ----------------
extern "C" void kernel_launch(void* const* d_in, const int* in_sizes, int n_in,
                              void* d_out, int out_size)
{
    const float* x   = (const float*)d_in[0];
    const int*   pos = (const int*)  d_in[1];
    const float* wq  = (const float*)d_in[2];
    const float* wk  = (const float*)d_in[3];
    const float* wv  = (const float*)d_in[4];
    const float* wo  = (const float*)d_in[5];
    const float* qw  = (const float*)d_in[6];
    const float* kw  = (const float*)d_in[7];
    float* out = (float*)d_out;

    float *xqg, *xk, *xv, *qn, *kn, *vt, *y;
    cudaGetSymbolAddress((void**)&xqg, g_xqg);
    cudaGetSymbolAddress((void**)&xk,  g_xk);
    cudaGetSymbolAddress((void**)&xv,  g_xv);
    cudaGetSymbolAddress((void**)&qn,  g_qn);
    cudaGetSymbolAddress((void**)&kn,  g_kn);
    cudaGetSymbolAddress((void**)&vt,  g_vt);
    cudaGetSymbolAddress((void**)&y,   g_y);

    sgemm128<<<dim3(QGN / 128, T_SEQ / 128), 256>>>(x, wq, xqg, T_SEQ, QGN, HID);
    sgemm128<<<dim3(KVN / 128, T_SEQ / 128), 256>>>(x, wk, xk, T_SEQ, KVN, HID);
    sgemm128<<<dim3(KVN / 128, T_SEQ / 128), 256>>>(x, wv, xv, T_SEQ, KVN, HID);
    normrope<<<dim3(T_SEQ, 24), 128>>>(xqg, xk, xv, pos, qw, kw, qn, kn, vt);
    attn<<<dim3(T_SEQ / 32, NQH), 256>>>(qn, kn, vt, xqg, y);
    sgemm128<<<dim3(HID / 128, T_SEQ / 128), 256>>>(y, wo, out, T_SEQ, HID, HID);
}

// round 4
// speedup vs baseline: 1.1698x; 1.1698x over previous
#include <cuda_runtime.h>
#include <math.h>

#define T_SEQ   2048
#define HID     2048
#define NQH     16
#define NKVH    4
#define HD      128
#define QGN     4096   // wq output width (q+gate)
#define KVN     512    // wk/wv output width

// ---------------- static scratch (no allocs allowed) ----------------
__device__ float g_xqg[T_SEQ * QGN];          // 32 MB  x@wq
__device__ float g_xk [T_SEQ * KVN];          //  4 MB  x@wk
__device__ float g_xv [T_SEQ * KVN];          //  4 MB  x@wv
__device__ float g_qn [NQH  * T_SEQ * HD];    // 16 MB  normed+roped q, head-major
__device__ float g_kn [NKVH * T_SEQ * HD];    //  4 MB
__device__ float g_vt [NKVH * T_SEQ * HD];    //  4 MB  v transposed head-major
__device__ float g_y  [T_SEQ * HID];          // 16 MB  gated attention out

// ---------------- tf32 helpers ----------------
__device__ __forceinline__ unsigned f2tf(float f) {
    unsigned u;
    asm("cvt.rna.tf32.f32 %0, %1;" : "=r"(u) : "f"(f));
    return u;
}

__device__ __forceinline__ void mma_tf32(float* c, const unsigned* a, const unsigned* b) {
    asm volatile(
        "mma.sync.aligned.m16n8k8.row.col.f32.tf32.tf32.f32 "
        "{%0,%1,%2,%3}, {%4,%5,%6,%7}, {%8,%9}, {%0,%1,%2,%3};"
        : "+f"(c[0]), "+f"(c[1]), "+f"(c[2]), "+f"(c[3])
        : "r"(a[0]), "r"(a[1]), "r"(a[2]), "r"(a[3]), "r"(b[0]), "r"(b[1]));
}

// ---------------- TF32 tensor-core GEMM ----------------
// C[M,N] = A[M,K] @ B[K,N], row-major, M%128==0, N%128==0, K%32==0.
// 128x128 block tile, BK=32, 256 threads, warp tile 64x32 (4x4 m16n8k8 frags).
// Smem stored k-major with word stride 136 -> bank (8k+col)%32, conflict-free
// for both the A and B fragment access patterns.
__global__ __launch_bounds__(256) void tf32gemm(
    const float* __restrict__ A, const float* __restrict__ B,
    float* __restrict__ C, int M, int N, int K)
{
    __shared__ __align__(16) unsigned As[32][136];  // As[k][m]
    __shared__ __align__(16) unsigned Bs[32][136];  // Bs[k][n]

    const int tid  = threadIdx.x;
    const int lane = tid & 31;
    const int warp = tid >> 5;
    const int wm = (warp >> 2) * 64;   // warp M offset: 0 / 64
    const int wn = (warp & 3) * 32;    // warp N offset: 0..96
    const int bm = blockIdx.y * 128, bn = blockIdx.x * 128;

    const float* Abase = A + (size_t)bm * K;
    const float* Bbase = B + bn;

    float4 pa[4], pb[4];

    // prefetch tile 0
    #pragma unroll
    for (int i = 0; i < 4; i++) {
        int idx = tid + i * 256;
        int m = idx & 127, kg = idx >> 7;           // A: 128 rows x 8 k-groups
        pa[i] = *(const float4*)(Abase + (size_t)m * K + kg * 4);
        int kr = idx >> 5, ng = idx & 31;           // B: 32 k-rows x 32 n-groups
        pb[i] = *(const float4*)(Bbase + (size_t)kr * N + ng * 4);
    }

    float acc[4][4][4];
    #pragma unroll
    for (int mf = 0; mf < 4; mf++)
        #pragma unroll
        for (int nf = 0; nf < 4; nf++)
            #pragma unroll
            for (int r = 0; r < 4; r++) acc[mf][nf][r] = 0.f;

    const int kb0 = lane & 3;
    const int rb  = lane >> 2;

    for (int k0 = 0; k0 < K; k0 += 32) {
        __syncthreads();
        // store prefetched tile to smem (convert to tf32 here, once)
        #pragma unroll
        for (int i = 0; i < 4; i++) {
            int idx = tid + i * 256;
            int m = idx & 127, kg = idx >> 7;
            As[kg * 4 + 0][m] = f2tf(pa[i].x);
            As[kg * 4 + 1][m] = f2tf(pa[i].y);
            As[kg * 4 + 2][m] = f2tf(pa[i].z);
            As[kg * 4 + 3][m] = f2tf(pa[i].w);
            int kr = idx >> 5, ng = idx & 31;
            Bs[kr][ng * 4 + 0] = f2tf(pb[i].x);
            Bs[kr][ng * 4 + 1] = f2tf(pb[i].y);
            Bs[kr][ng * 4 + 2] = f2tf(pb[i].z);
            Bs[kr][ng * 4 + 3] = f2tf(pb[i].w);
        }
        __syncthreads();

        // prefetch next tile (overlaps with compute below)
        if (k0 + 32 < K) {
            #pragma unroll
            for (int i = 0; i < 4; i++) {
                int idx = tid + i * 256;
                int m = idx & 127, kg = idx >> 7;
                pa[i] = *(const float4*)(Abase + (size_t)m * K + k0 + 32 + kg * 4);
                int kr = idx >> 5, ng = idx & 31;
                pb[i] = *(const float4*)(Bbase + (size_t)(k0 + 32 + kr) * N + ng * 4);
            }
        }

        // compute: 4 k-steps of 8
        #pragma unroll
        for (int ks = 0; ks < 4; ks++) {
            const int kb = ks * 8 + kb0;
            unsigned a[4][4], b[4][2];
            #pragma unroll
            for (int mf = 0; mf < 4; mf++) {
                int m = wm + mf * 16 + rb;
                a[mf][0] = As[kb][m];
                a[mf][1] = As[kb][m + 8];
                a[mf][2] = As[kb + 4][m];
                a[mf][3] = As[kb + 4][m + 8];
            }
            #pragma unroll
            for (int nf = 0; nf < 4; nf++) {
                int n = wn + nf * 8 + rb;
                b[nf][0] = Bs[kb][n];
                b[nf][1] = Bs[kb + 4][n];
            }
            #pragma unroll
            for (int mf = 0; mf < 4; mf++)
                #pragma unroll
                for (int nf = 0; nf < 4; nf++)
                    mma_tf32(acc[mf][nf], a[mf], b[nf]);
        }
    }

    // epilogue
    #pragma unroll
    for (int mf = 0; mf < 4; mf++) {
        #pragma unroll
        for (int nf = 0; nf < 4; nf++) {
            int row = bm + wm + mf * 16 + rb;
            int col = bn + wn + nf * 8 + 2 * kb0;
            *(float2*)(C + (size_t)row * N + col) =
                make_float2(acc[mf][nf][0], acc[mf][nf][1]);
            *(float2*)(C + (size_t)(row + 8) * N + col) =
                make_float2(acc[mf][nf][2], acc[mf][nf][3]);
        }
    }
}

// ---------------- RMSNorm + RoPE + transpose-to-head-major ----------------
// grid: (T_SEQ, 24). jobs 0-15: q heads, 16-19: k heads, 20-23: v copy.
__global__ __launch_bounds__(128) void normrope(
    const float* __restrict__ xqg, const float* __restrict__ xk,
    const float* __restrict__ xv,  const int* __restrict__ input_pos,
    const float* __restrict__ qw,  const float* __restrict__ kw,
    float* __restrict__ qn, float* __restrict__ kn, float* __restrict__ vt)
{
    const int t = blockIdx.x;
    const int job = blockIdx.y;
    const int d = threadIdx.x;

    if (job >= 20) {  // v: plain transpose
        int h = job - 20;
        vt[((size_t)h * T_SEQ + t) * HD + d] = xv[(size_t)t * KVN + h * HD + d];
        return;
    }

    const float* src;
    const float* w;
    float* dst;
    if (job < 16) {
        src = xqg + (size_t)t * QGN + job * 256;      // q part of q|gate
        w = qw;
        dst = qn + ((size_t)job * T_SEQ + t) * HD;
    } else {
        int h = job - 16;
        src = xk + (size_t)t * KVN + h * HD;
        w = kw;
        dst = kn + ((size_t)h * T_SEQ + t) * HD;
    }

    float v = src[d];
    float ss = v * v;
    #pragma unroll
    for (int o = 16; o; o >>= 1) ss += __shfl_xor_sync(0xffffffffu, ss, o);

    __shared__ float warpss[4];
    __shared__ float sh[HD];
    if ((d & 31) == 0) warpss[d >> 5] = ss;
    __syncthreads();
    float tot = warpss[0] + warpss[1] + warpss[2] + warpss[3];
    float nv = v * rsqrtf(tot * (1.f / HD) + 1e-6f) * (1.f + w[d]);
    sh[d] = nv;
    __syncthreads();

    float out;
    if (d < 64) {
        int i = d & 31;                       // rotary pair index
        // inv_freq = 10000^{-i/32}
        float inv = __expf(-(float)i * (9.210340371976184f / 32.f));
        float ang = (float)input_pos[t] * inv;
        float c = cosf(ang), s = sinf(ang);
        if (d < 32) out = sh[d] * c - sh[d + 32] * s;
        else        out = sh[d] * c + sh[d - 32] * s;
    } else {
        out = nv;
    }
    dst[d] = out;
}

// ---------------- flash attention (causal, GQA) + sigmoid gate ----------------
// grid: (T_SEQ/32, NQH). 256 threads. Bq=32, Bk=32.
__global__ __launch_bounds__(256) void attn(
    const float* __restrict__ qn, const float* __restrict__ kn,
    const float* __restrict__ vt, const float* __restrict__ xqg,
    float* __restrict__ y)
{
    const int h = blockIdx.y;
    const int kvh = h >> 2;
    const int q0 = blockIdx.x * 32;

    __shared__ __align__(16) float Qs[32][132];
    __shared__ __align__(16) float KV[32][132];
    __shared__ float Ps[32][32];

    const int t = threadIdx.x;

    // load Q tile: 1024 float4s over 256 threads
    #pragma unroll
    for (int i = 0; i < 4; i++) {
        int fi = t + i * 256;
        int r = fi >> 5, c4 = fi & 31;
        *(float4*)&Qs[r][c4 * 4] =
            *(const float4*)(qn + ((size_t)h * T_SEQ + q0 + r) * HD + c4 * 4);
    }

    const int qr = t >> 3;          // query row 0..31 (8 threads per row)
    const int c0 = (t & 7) * 4;     // score cols
    const int d0 = (t & 7) * 16;    // output dims

    float m = -1e30f, l = 0.f;
    float acc[16];
    #pragma unroll
    for (int i = 0; i < 16; i++) acc[i] = 0.f;

    const int ntiles = (q0 >> 5) + 1;
    const float scale = 0.08838834764831845f;  // 1/sqrt(128)

    for (int kt = 0; kt < ntiles; kt++) {
        const int k0 = kt * 32;
        __syncthreads();   // protect KV from previous PV readers
        #pragma unroll
        for (int i = 0; i < 4; i++) {
            int fi = t + i * 256;
            int r = fi >> 5, c4 = fi & 31;
            *(float4*)&KV[r][c4 * 4] =
                *(const float4*)(kn + ((size_t)kvh * T_SEQ + k0 + r) * HD + c4 * 4);
        }
        __syncthreads();

        float s[4] = {0.f, 0.f, 0.f, 0.f};
        #pragma unroll 8
        for (int kk = 0; kk < 32; kk++) {
            float4 q4 = *(const float4*)&Qs[qr][kk * 4];
            #pragma unroll
            for (int j = 0; j < 4; j++) {
                float4 k4 = *(const float4*)&KV[c0 + j][kk * 4];
                s[j] += q4.x * k4.x + q4.y * k4.y + q4.z * k4.z + q4.w * k4.w;
            }
        }
        #pragma unroll
        for (int j = 0; j < 4; j++) {
            int kcol = k0 + c0 + j;
            float sv = s[j] * scale;
            s[j] = (kcol > q0 + qr) ? -1e30f : sv;
        }
        float rowmax = fmaxf(fmaxf(s[0], s[1]), fmaxf(s[2], s[3]));
        #pragma unroll
        for (int o = 1; o < 8; o <<= 1)
            rowmax = fmaxf(rowmax, __shfl_xor_sync(0xffffffffu, rowmax, o));

        float mn = fmaxf(m, rowmax);
        float corr = __expf(m - mn);
        float p[4], ps = 0.f;
        #pragma unroll
        for (int j = 0; j < 4; j++) { p[j] = __expf(s[j] - mn); ps += p[j]; }
        #pragma unroll
        for (int o = 1; o < 8; o <<= 1) ps += __shfl_xor_sync(0xffffffffu, ps, o);
        l = l * corr + ps;
        m = mn;
        #pragma unroll
        for (int i = 0; i < 16; i++) acc[i] *= corr;
        #pragma unroll
        for (int j = 0; j < 4; j++) Ps[qr][c0 + j] = p[j];
        __syncthreads();

        // load V tile into same buffer
        #pragma unroll
        for (int i = 0; i < 4; i++) {
            int fi = t + i * 256;
            int r = fi >> 5, c4 = fi & 31;
            *(float4*)&KV[r][c4 * 4] =
                *(const float4*)(vt + ((size_t)kvh * T_SEQ + k0 + r) * HD + c4 * 4);
        }
        __syncthreads();

        #pragma unroll 8
        for (int c = 0; c < 32; c++) {
            float pv = Ps[qr][c];
            float4 v0 = *(const float4*)&KV[c][d0];
            float4 v1 = *(const float4*)&KV[c][d0 + 4];
            float4 v2 = *(const float4*)&KV[c][d0 + 8];
            float4 v3 = *(const float4*)&KV[c][d0 + 12];
            acc[0]  += pv * v0.x; acc[1]  += pv * v0.y; acc[2]  += pv * v0.z; acc[3]  += pv * v0.w;
            acc[4]  += pv * v1.x; acc[5]  += pv * v1.y; acc[6]  += pv * v1.z; acc[7]  += pv * v1.w;
            acc[8]  += pv * v2.x; acc[9]  += pv * v2.y; acc[10] += pv * v2.z; acc[11] += pv * v2.w;
            acc[12] += pv * v3.x; acc[13] += pv * v3.y; acc[14] += pv * v3.z; acc[15] += pv * v3.w;
        }
    }

    const float invl = 1.f / l;
    const int tok = q0 + qr;
    const float* gp = xqg + (size_t)tok * QGN + h * 256 + 128 + d0;
    float* yp = y + (size_t)tok * HID + h * HD + d0;
    #pragma unroll
    for (int i = 0; i < 16; i++) {
        float g = gp[i];
        float sg = 1.f / (1.f + __expf(-g));
        yp[i] = acc[i] * invl * sg;
    }
}

// ---------------- launch ----------------
extern "C" void kernel_launch(void* const* d_in, const int* in_sizes, int n_in,
                              void* d_out, int out_size)
{
    const float* x   = (const float*)d_in[0];
    const int*   pos = (const int*)  d_in[1];
    const float* wq  = (const float*)d_in[2];
    const float* wk  = (const float*)d_in[3];
    const float* wv  = (const float*)d_in[4];
    const float* wo  = (const float*)d_in[5];
    const float* qw  = (const float*)d_in[6];
    const float* kw  = (const float*)d_in[7];
    float* out = (float*)d_out;

    float *xqg, *xk, *xv, *qn, *kn, *vt, *y;
    cudaGetSymbolAddress((void**)&xqg, g_xqg);
    cudaGetSymbolAddress((void**)&xk,  g_xk);
    cudaGetSymbolAddress((void**)&xv,  g_xv);
    cudaGetSymbolAddress((void**)&qn,  g_qn);
    cudaGetSymbolAddress((void**)&kn,  g_kn);
    cudaGetSymbolAddress((void**)&vt,  g_vt);
    cudaGetSymbolAddress((void**)&y,   g_y);

    tf32gemm<<<dim3(QGN / 128, T_SEQ / 128), 256>>>(x, wq, xqg, T_SEQ, QGN, HID);
    tf32gemm<<<dim3(KVN / 128, T_SEQ / 128), 256>>>(x, wk, xk, T_SEQ, KVN, HID);
    tf32gemm<<<dim3(KVN / 128, T_SEQ / 128), 256>>>(x, wv, xv, T_SEQ, KVN, HID);
    normrope<<<dim3(T_SEQ, 24), 128>>>(xqg, xk, xv, pos, qw, kw, qn, kn, vt);
    attn<<<dim3(T_SEQ / 32, NQH), 256>>>(qn, kn, vt, xqg, y);
    tf32gemm<<<dim3(HID / 128, T_SEQ / 128), 256>>>(y, wo, out, T_SEQ, HID, HID);
}

// round 16
// speedup vs baseline: 1.2134x; 1.0372x over previous
#include <cuda_runtime.h>
#include <cuda_fp16.h>
#include <cstdint>
#include <math.h>

#define T_SEQ   2048
#define HID     2048
#define NQH     16
#define NKVH    4
#define HD      128
#define QGN     4096
#define KVN     512

// ---------------- static scratch ----------------
__device__ float g_xqg[T_SEQ * QGN];
__device__ float g_xk [T_SEQ * KVN];
__device__ float g_xv [T_SEQ * KVN];
__device__ float g_qn [NQH  * T_SEQ * HD];
__device__ float g_kn [NKVH * T_SEQ * HD];
__device__ float g_vt [NKVH * T_SEQ * HD];
__device__ float g_y  [T_SEQ * HID];

// ---------------- fp16 mma (m16n8k16, fp32 accumulate) ----------------
__device__ __forceinline__ void mma_f16(float* c, const uint32_t* a, const uint32_t* b) {
    asm volatile(
        "mma.sync.aligned.m16n8k16.row.col.f32.f16.f16.f32 "
        "{%0,%1,%2,%3}, {%4,%5,%6,%7}, {%8,%9}, {%0,%1,%2,%3};"
        : "+f"(c[0]), "+f"(c[1]), "+f"(c[2]), "+f"(c[3])
        : "r"(a[0]), "r"(a[1]), "r"(a[2]), "r"(a[3]), "r"(b[0]), "r"(b[1]));
}

__device__ __forceinline__ uint32_t h2u(__half2 h) {
    return *reinterpret_cast<uint32_t*>(&h);
}

// ---------------- FP16 tensor-core GEMM ----------------
// C[M,N] = A[M,K] @ B[K,N], row-major fp32 in/out, fp16 mma, fp32 accum.
// 128x128 block tile, BK=32, 256 threads, warp tile 64x32 (4x4 m16n8k16 frags).
// Smem: half2-packed k-pairs, [kp][col] with word stride 136 -> bank
// (8*kp + col) % 32, conflict-free for A and B fragment reads.
// B tile stored via 2x STS.128 per thread (contiguous 8-column octet).
__global__ __launch_bounds__(256) void hgemm(
    const float* __restrict__ A, const float* __restrict__ B,
    float* __restrict__ C, int M, int N, int K)
{
    __shared__ __align__(16) uint32_t As[16][136];  // As[kp][m] = half2(k=2kp, 2kp+1)
    __shared__ __align__(16) uint32_t Bs[16][136];  // Bs[kp][n]

    const int tid  = threadIdx.x;
    const int lane = tid & 31;
    const int warp = tid >> 5;
    const int wm = (warp >> 2) * 64;   // warp M offset: 0 / 64
    const int wn = (warp & 3) * 32;    // warp N offset: 0..96
    const int bm = blockIdx.y * 128, bn = blockIdx.x * 128;

    const float* Abase = A + (size_t)bm * K;
    const float* Bbase = B + bn;

    // A loader: thread covers row am, k-groups kg = 2i + (tid>>7), 4 floats each
    const int am  = tid & 127;
    const int akg = tid >> 7;
    // B loader: thread covers k-pair row bkp, n-octet bn0 (rows 2bkp, 2bkp+1)
    const int bkp = tid >> 4;
    const int bn0 = (tid & 15) * 8;

    float4 pa[4], pb[4];

    // prefetch chunk 0
    #pragma unroll
    for (int i = 0; i < 4; i++)
        pa[i] = *(const float4*)(Abase + (size_t)am * K + (2 * i + akg) * 4);
    {
        const float* b0 = Bbase + (size_t)(2 * bkp) * N + bn0;
        pb[0] = *(const float4*)(b0);
        pb[1] = *(const float4*)(b0 + 4);
        pb[2] = *(const float4*)(b0 + N);
        pb[3] = *(const float4*)(b0 + N + 4);
    }

    float acc[4][4][4];
    #pragma unroll
    for (int mf = 0; mf < 4; mf++)
        #pragma unroll
        for (int nf = 0; nf < 4; nf++)
            #pragma unroll
            for (int r = 0; r < 4; r++) acc[mf][nf][r] = 0.f;

    const int kb0 = lane & 3;
    const int rb  = lane >> 2;

    for (int k0 = 0; k0 < K; k0 += 32) {
        __syncthreads();
        // store prefetched chunk to smem as half2 k-pairs
        #pragma unroll
        for (int i = 0; i < 4; i++) {
            int kg = 2 * i + akg;
            __half2 h0 = __floats2half2_rn(pa[i].x, pa[i].y);
            __half2 h1 = __floats2half2_rn(pa[i].z, pa[i].w);
            As[kg * 2][am]     = h2u(h0);
            As[kg * 2 + 1][am] = h2u(h1);
        }
        {
            // columns bn0..bn0+7: half2(row 2bkp val, row 2bkp+1 val), packed
            // into two 128-bit stores (same bytes/addresses as scalar stores).
            uint4 q0 = make_uint4(
                h2u(__floats2half2_rn(pb[0].x, pb[2].x)),
                h2u(__floats2half2_rn(pb[0].y, pb[2].y)),
                h2u(__floats2half2_rn(pb[0].z, pb[2].z)),
                h2u(__floats2half2_rn(pb[0].w, pb[2].w)));
            uint4 q1 = make_uint4(
                h2u(__floats2half2_rn(pb[1].x, pb[3].x)),
                h2u(__floats2half2_rn(pb[1].y, pb[3].y)),
                h2u(__floats2half2_rn(pb[1].z, pb[3].z)),
                h2u(__floats2half2_rn(pb[1].w, pb[3].w)));
            *(uint4*)&Bs[bkp][bn0]     = q0;
            *(uint4*)&Bs[bkp][bn0 + 4] = q1;
        }
        __syncthreads();

        // prefetch next chunk (overlaps compute)
        if (k0 + 32 < K) {
            #pragma unroll
            for (int i = 0; i < 4; i++)
                pa[i] = *(const float4*)(Abase + (size_t)am * K + k0 + 32 + (2 * i + akg) * 4);
            const float* b0 = Bbase + (size_t)(k0 + 32 + 2 * bkp) * N + bn0;
            pb[0] = *(const float4*)(b0);
            pb[1] = *(const float4*)(b0 + 4);
            pb[2] = *(const float4*)(b0 + N);
            pb[3] = *(const float4*)(b0 + N + 4);
        }

        // compute: 2 k-steps of 16
        #pragma unroll
        for (int ks = 0; ks < 2; ks++) {
            const int kb = ks * 8 + kb0;
            uint32_t a[4][4], b[4][2];
            #pragma unroll
            for (int mf = 0; mf < 4; mf++) {
                int m = wm + mf * 16 + rb;
                a[mf][0] = As[kb][m];
                a[mf][1] = As[kb][m + 8];
                a[mf][2] = As[kb + 4][m];
                a[mf][3] = As[kb + 4][m + 8];
            }
            #pragma unroll
            for (int nf = 0; nf < 4; nf++) {
                int n = wn + nf * 8 + rb;
                b[nf][0] = Bs[kb][n];
                b[nf][1] = Bs[kb + 4][n];
            }
            #pragma unroll
            for (int mf = 0; mf < 4; mf++)
                #pragma unroll
                for (int nf = 0; nf < 4; nf++)
                    mma_f16(acc[mf][nf], a[mf], b[nf]);
        }
    }

    // epilogue
    #pragma unroll
    for (int mf = 0; mf < 4; mf++) {
        #pragma unroll
        for (int nf = 0; nf < 4; nf++) {
            int row = bm + wm + mf * 16 + rb;
            int col = bn + wn + nf * 8 + 2 * kb0;
            *(float2*)(C + (size_t)row * N + col) =
                make_float2(acc[mf][nf][0], acc[mf][nf][1]);
            *(float2*)(C + (size_t)(row + 8) * N + col) =
                make_float2(acc[mf][nf][2], acc[mf][nf][3]);
        }
    }
}

// ---------------- RMSNorm + RoPE + transpose-to-head-major ----------------
__global__ __launch_bounds__(128) void normrope(
    const float* __restrict__ xqg, const float* __restrict__ xk,
    const float* __restrict__ xv,  const int* __restrict__ input_pos,
    const float* __restrict__ qw,  const float* __restrict__ kw,
    float* __restrict__ qn, float* __restrict__ kn, float* __restrict__ vt)
{
    const int t = blockIdx.x;
    const int job = blockIdx.y;
    const int d = threadIdx.x;

    if (job >= 20) {
        int h = job - 20;
        vt[((size_t)h * T_SEQ + t) * HD + d] = xv[(size_t)t * KVN + h * HD + d];
        return;
    }

    const float* src;
    const float* w;
    float* dst;
    if (job < 16) {
        src = xqg + (size_t)t * QGN + job * 256;
        w = qw;
        dst = qn + ((size_t)job * T_SEQ + t) * HD;
    } else {
        int h = job - 16;
        src = xk + (size_t)t * KVN + h * HD;
        w = kw;
        dst = kn + ((size_t)h * T_SEQ + t) * HD;
    }

    float v = src[d];
    float ss = v * v;
    #pragma unroll
    for (int o = 16; o; o >>= 1) ss += __shfl_xor_sync(0xffffffffu, ss, o);

    __shared__ float warpss[4];
    __shared__ float sh[HD];
    if ((d & 31) == 0) warpss[d >> 5] = ss;
    __syncthreads();
    float tot = warpss[0] + warpss[1] + warpss[2] + warpss[3];
    float nv = v * rsqrtf(tot * (1.f / HD) + 1e-6f) * (1.f + w[d]);
    sh[d] = nv;
    __syncthreads();

    float out;
    if (d < 64) {
        int i = d & 31;
        float inv = __expf(-(float)i * (9.210340371976184f / 32.f));
        float ang = (float)input_pos[t] * inv;
        float c = cosf(ang), s = sinf(ang);
        if (d < 32) out = sh[d] * c - sh[d + 32] * s;
        else        out = sh[d] * c + sh[d - 32] * s;
    } else {
        out = nv;
    }
    dst[d] = out;
}

// ---------------- flash attention (causal, GQA) + sigmoid gate ----------------
__global__ __launch_bounds__(256) void attn(
    const float* __restrict__ qn, const float* __restrict__ kn,
    const float* __restrict__ vt, const float* __restrict__ xqg,
    float* __restrict__ y)
{
    const int h = blockIdx.y;
    const int kvh = h >> 2;
    const int q0 = blockIdx.x * 32;

    __shared__ __align__(16) float Qs[32][132];
    __shared__ __align__(16) float KV[32][132];
    __shared__ float Ps[32][32];

    const int t = threadIdx.x;

    #pragma unroll
    for (int i = 0; i < 4; i++) {
        int fi = t + i * 256;
        int r = fi >> 5, c4 = fi & 31;
        *(float4*)&Qs[r][c4 * 4] =
            *(const float4*)(qn + ((size_t)h * T_SEQ + q0 + r) * HD + c4 * 4);
    }

    const int qr = t >> 3;
    const int c0 = (t & 7) * 4;
    const int d0 = (t & 7) * 16;

    float m = -1e30f, l = 0.f;
    float acc[16];
    #pragma unroll
    for (int i = 0; i < 16; i++) acc[i] = 0.f;

    const int ntiles = (q0 >> 5) + 1;
    const float scale = 0.08838834764831845f;

    for (int kt = 0; kt < ntiles; kt++) {
        const int k0 = kt * 32;
        __syncthreads();
        #pragma unroll
        for (int i = 0; i < 4; i++) {
            int fi = t + i * 256;
            int r = fi >> 5, c4 = fi & 31;
            *(float4*)&KV[r][c4 * 4] =
                *(const float4*)(kn + ((size_t)kvh * T_SEQ + k0 + r) * HD + c4 * 4);
        }
        __syncthreads();

        float s[4] = {0.f, 0.f, 0.f, 0.f};
        #pragma unroll 8
        for (int kk = 0; kk < 32; kk++) {
            float4 q4 = *(const float4*)&Qs[qr][kk * 4];
            #pragma unroll
            for (int j = 0; j < 4; j++) {
                float4 k4 = *(const float4*)&KV[c0 + j][kk * 4];
                s[j] += q4.x * k4.x + q4.y * k4.y + q4.z * k4.z + q4.w * k4.w;
            }
        }
        #pragma unroll
        for (int j = 0; j < 4; j++) {
            int kcol = k0 + c0 + j;
            float sv = s[j] * scale;
            s[j] = (kcol > q0 + qr) ? -1e30f : sv;
        }
        float rowmax = fmaxf(fmaxf(s[0], s[1]), fmaxf(s[2], s[3]));
        #pragma unroll
        for (int o = 1; o < 8; o <<= 1)
            rowmax = fmaxf(rowmax, __shfl_xor_sync(0xffffffffu, rowmax, o));

        float mn = fmaxf(m, rowmax);
        float corr = __expf(m - mn);
        float p[4], ps = 0.f;
        #pragma unroll
        for (int j = 0; j < 4; j++) { p[j] = __expf(s[j] - mn); ps += p[j]; }
        #pragma unroll
        for (int o = 1; o < 8; o <<= 1) ps += __shfl_xor_sync(0xffffffffu, ps, o);
        l = l * corr + ps;
        m = mn;
        #pragma unroll
        for (int i = 0; i < 16; i++) acc[i] *= corr;
        #pragma unroll
        for (int j = 0; j < 4; j++) Ps[qr][c0 + j] = p[j];
        __syncthreads();

        #pragma unroll
        for (int i = 0; i < 4; i++) {
            int fi = t + i * 256;
            int r = fi >> 5, c4 = fi & 31;
            *(float4*)&KV[r][c4 * 4] =
                *(const float4*)(vt + ((size_t)kvh * T_SEQ + k0 + r) * HD + c4 * 4);
        }
        __syncthreads();

        #pragma unroll 8
        for (int c = 0; c < 32; c++) {
            float pv = Ps[qr][c];
            float4 v0 = *(const float4*)&KV[c][d0];
            float4 v1 = *(const float4*)&KV[c][d0 + 4];
            float4 v2 = *(const float4*)&KV[c][d0 + 8];
            float4 v3 = *(const float4*)&KV[c][d0 + 12];
            acc[0]  += pv * v0.x; acc[1]  += pv * v0.y; acc[2]  += pv * v0.z; acc[3]  += pv * v0.w;
            acc[4]  += pv * v1.x; acc[5]  += pv * v1.y; acc[6]  += pv * v1.z; acc[7]  += pv * v1.w;
            acc[8]  += pv * v2.x; acc[9]  += pv * v2.y; acc[10] += pv * v2.z; acc[11] += pv * v2.w;
            acc[12] += pv * v3.x; acc[13] += pv * v3.y; acc[14] += pv * v3.z; acc[15] += pv * v3.w;
        }
    }

    const float invl = 1.f / l;
    const int tok = q0 + qr;
    const float* gp = xqg + (size_t)tok * QGN + h * 256 + 128 + d0;
    float* yp = y + (size_t)tok * HID + h * HD + d0;
    #pragma unroll
    for (int i = 0; i < 16; i++) {
        float g = gp[i];
        float sg = 1.f / (1.f + __expf(-g));
        yp[i] = acc[i] * invl * sg;
    }
}

// ---------------- launch ----------------
extern "C" void kernel_launch(void* const* d_in, const int* in_sizes, int n_in,
                              void* d_out, int out_size)
{
    const float* x   = (const float*)d_in[0];
    const int*   pos = (const int*)  d_in[1];
    const float* wq  = (const float*)d_in[2];
    const float* wk  = (const float*)d_in[3];
    const float* wv  = (const float*)d_in[4];
    const float* wo  = (const float*)d_in[5];
    const float* qw  = (const float*)d_in[6];
    const float* kw  = (const float*)d_in[7];
    float* out = (float*)d_out;

    float *xqg, *xk, *xv, *qn, *kn, *vt, *y;
    cudaGetSymbolAddress((void**)&xqg, g_xqg);
    cudaGetSymbolAddress((void**)&xk,  g_xk);
    cudaGetSymbolAddress((void**)&xv,  g_xv);
    cudaGetSymbolAddress((void**)&qn,  g_qn);
    cudaGetSymbolAddress((void**)&kn,  g_kn);
    cudaGetSymbolAddress((void**)&vt,  g_vt);
    cudaGetSymbolAddress((void**)&y,   g_y);

    hgemm<<<dim3(QGN / 128, T_SEQ / 128), 256>>>(x, wq, xqg, T_SEQ, QGN, HID);
    hgemm<<<dim3(KVN / 128, T_SEQ / 128), 256>>>(x, wk, xk, T_SEQ, KVN, HID);
    hgemm<<<dim3(KVN / 128, T_SEQ / 128), 256>>>(x, wv, xv, T_SEQ, KVN, HID);
    normrope<<<dim3(T_SEQ, 24), 128>>>(xqg, xk, xv, pos, qw, kw, qn, kn, vt);
    attn<<<dim3(T_SEQ / 32, NQH), 256>>>(qn, kn, vt, xqg, y);
    hgemm<<<dim3(HID / 128, T_SEQ / 128), 256>>>(y, wo, out, T_SEQ, HID, HID);
}